// round 16
// baseline (speedup 1.0000x reference)
#include <cuda_runtime.h>
#include <cuda_bf16.h>
#include <cstdint>
#include <math.h>

// ============================================================================
// Problem dims (fixed by the dataset): x [2,4096,4096] -> T=8192 tokens
// ============================================================================
#define T_TOK 8192
#define H_DIM 4096
#define I_DIM 2048

// Harness ptxas targets plain sm_103 (no 'a'): baseline-ISA tensor path.
// R16 = R15 (best) + two mainloop scheduling tweaks:
//  (a) cp.async issuance interleaved across the 4 k-steps (smooths crossbar
//      write bursts against LDSM reads),
//  (b) non-volatile MMA asm (ptxas may overlap LDSM with trailing HMMAs,
//      bounded by the 128-reg cap -- no manual double buffer, unlike R11).
//
// Numerics model (XLA CPU fast-math = arcp+contract), validated in R6:
//  - scale = amax * RN(1/127), fmax 1e-8
//  - q = xs * (1.0/scale)_exact_div, rintf (round-half-even)
//  - silu: logistic = 0.5 + 0.5*tanh(0.5x), EmitFastTanh poly, FMA-contracted

static __device__ __forceinline__ float rcp127() { return 1.0f / 127.0f; }

__device__ __forceinline__ float xla_fast_tanh(float x) {
    const float kMax = 7.90531110763549805f;
    float cl = fminf(fmaxf(x, -kMax), kMax);
    float x2 = __fmul_rn(cl, cl);
    float p = -2.76076847742355e-16f;
    p = __fmaf_rn(x2, p, 2.00018790482477e-13f);
    p = __fmaf_rn(x2, p, -8.60467152213735e-11f);
    p = __fmaf_rn(x2, p, 5.12229709037114e-08f);
    p = __fmaf_rn(x2, p, 1.48572235717979e-05f);
    p = __fmaf_rn(x2, p, 6.37261928875436e-04f);
    p = __fmaf_rn(x2, p, 4.89352455891786e-03f);
    p = __fmul_rn(cl, p);
    float q = 1.19825839466702e-06f;
    q = __fmaf_rn(x2, q, 1.18534705686654e-04f);
    q = __fmaf_rn(x2, q, 2.26843463243900e-03f);
    q = __fmaf_rn(x2, q, 4.89352518554385e-03f);
    return (fabsf(x) < 0.0004f) ? x : __fdiv_rn(p, q);
}

__device__ __forceinline__ float xla_silu(float x) {
    float t = xla_fast_tanh(__fmul_rn(0.5f, x));
    float sig = __fmaf_rn(0.5f, t, 0.5f);
    return __fmul_rn(x, sig);
}

// ============================================================================
// PTX helpers
// ============================================================================
__device__ __forceinline__ uint32_t smem_to_u32(const void* smem_ptr) {
    uint32_t addr;
    asm("{ .reg .u64 tmp; cvta.to.shared.u64 tmp, %1; cvt.u32.u64 %0, tmp; }"
        : "=r"(addr) : "l"(smem_ptr));
    return addr;
}

#define SMEM_SWIZZLE_128B(byte_offset) \
    ((uint32_t)(byte_offset) ^ ((((uint32_t)(byte_offset)) >> 3) & 0x70u))

#define CP_ASYNC_16(smem_u32, gptr) \
    asm volatile("cp.async.cg.shared.global [%0], [%1], 16;" \
        :: "r"(smem_u32), "l"(gptr) : "memory")

#define CP_ASYNC_COMMIT() asm volatile("cp.async.commit_group;" ::: "memory")
#define CP_ASYNC_WAIT_1() asm volatile("cp.async.wait_group 1;" ::: "memory")

__device__ __forceinline__ void ldsm_x4(uint32_t& r0, uint32_t& r1,
                                        uint32_t& r2, uint32_t& r3,
                                        uint32_t smem_addr) {
    asm volatile(
        "ldmatrix.sync.aligned.m8n8.x4.shared.b16 {%0,%1,%2,%3}, [%4];"
        : "=r"(r0), "=r"(r1), "=r"(r2), "=r"(r3)
        : "r"(smem_addr));
}

// Non-volatile: register dependencies order it; ptxas may schedule freely.
__device__ __forceinline__ void mma16816(float* c, const uint32_t* a,
                                         uint32_t b0, uint32_t b1) {
    asm("mma.sync.aligned.m16n8k16.row.col.f32.bf16.bf16.f32 "
        "{%0,%1,%2,%3}, {%4,%5,%6,%7}, {%8,%9}, {%0,%1,%2,%3};"
        : "+f"(c[0]), "+f"(c[1]), "+f"(c[2]), "+f"(c[3])
        : "r"(a[0]), "r"(a[1]), "r"(a[2]), "r"(a[3]), "r"(b0), "r"(b1));
}

// ============================================================================
// Device scratch (static globals: allocation-guard-safe)
// ============================================================================
__device__ __nv_bfloat16 g_qg[(size_t)T_TOK * H_DIM];
__device__ __nv_bfloat16 g_qu[(size_t)T_TOK * H_DIM];
__device__ __nv_bfloat16 g_wg[(size_t)I_DIM * H_DIM];
__device__ __nv_bfloat16 g_wu[(size_t)I_DIM * H_DIM];
__device__ __nv_bfloat16 g_wd[(size_t)H_DIM * I_DIM];
__device__ float g_gate[(size_t)T_TOK * I_DIM];
__device__ float g_up[(size_t)T_TOK * I_DIM];
__device__ __nv_bfloat16 g_qi[(size_t)T_TOK * I_DIM];
__device__ float g_sg[T_TOK];
__device__ float g_su[T_TOK];
__device__ float g_si[T_TOK];

// Pack 4 floats -> 4 bf16 in a uint2
__device__ __forceinline__ uint2 pack4_bf16(float a, float b, float c, float d) {
    __nv_bfloat162 lo = __floats2bfloat162_rn(a, b);
    __nv_bfloat162 hi = __floats2bfloat162_rn(c, d);
    uint2 r;
    r.x = *(uint32_t*)&lo;
    r.y = *(uint32_t*)&hi;
    return r;
}

// ============================================================================
// Kernel 0: f32 -> bf16 convert for ALL THREE weights in one launch.
// ============================================================================
#define W_N4 (I_DIM * H_DIM / 4)
__global__ void cvt_weights_kernel(const float4* __restrict__ in0,
                                   const float4* __restrict__ in1,
                                   const float4* __restrict__ in2,
                                   uint2* __restrict__ out0,
                                   uint2* __restrict__ out1,
                                   uint2* __restrict__ out2)
{
    int i = blockIdx.x * blockDim.x + threadIdx.x;
    int stride = gridDim.x * blockDim.x;
    for (; i < 3 * W_N4; i += stride) {
        const float4* in; uint2* out; int j;
        if (i < W_N4)            { in = in0; out = out0; j = i; }
        else if (i < 2 * W_N4)   { in = in1; out = out1; j = i - W_N4; }
        else                     { in = in2; out = out2; j = i - 2 * W_N4; }
        float4 v = in[j];
        out[j] = pack4_bf16(v.x, v.y, v.z, v.w);
    }
}

// ============================================================================
// Kernel 1: per-token dual dynamic quant of x -> bf16 ints (one pass)
// ============================================================================
__global__ void __launch_bounds__(256) quant_x_kernel(
    const float* __restrict__ x,
    const float* __restrict__ invg,
    const float* __restrict__ invu,
    __nv_bfloat16* __restrict__ qg,
    __nv_bfloat16* __restrict__ qu,
    float* __restrict__ sg,
    float* __restrict__ su)
{
    __shared__ float red_g[8];
    __shared__ float red_u[8];

    const int row = blockIdx.x;
    const float4* xr = (const float4*)(x + (size_t)row * H_DIM);
    const float4* g4 = (const float4*)invg;
    const float4* u4 = (const float4*)invu;

    float xsg[16], xsu[16];
    float amg = 0.f, amu = 0.f;
    #pragma unroll
    for (int j = 0; j < 4; j++) {
        int idx = threadIdx.x + j * 256;
        float4 v = xr[idx];
        float4 gi = g4[idx];
        float4 ui = u4[idx];
        float f0 = __bfloat162float(__float2bfloat16(v.x));
        float f1 = __bfloat162float(__float2bfloat16(v.y));
        float f2 = __bfloat162float(__float2bfloat16(v.z));
        float f3 = __bfloat162float(__float2bfloat16(v.w));
        xsg[j*4+0] = __fmul_rn(f0, gi.x); xsg[j*4+1] = __fmul_rn(f1, gi.y);
        xsg[j*4+2] = __fmul_rn(f2, gi.z); xsg[j*4+3] = __fmul_rn(f3, gi.w);
        xsu[j*4+0] = __fmul_rn(f0, ui.x); xsu[j*4+1] = __fmul_rn(f1, ui.y);
        xsu[j*4+2] = __fmul_rn(f2, ui.z); xsu[j*4+3] = __fmul_rn(f3, ui.w);
        #pragma unroll
        for (int k = 0; k < 4; k++) {
            amg = fmaxf(amg, fabsf(xsg[j*4+k]));
            amu = fmaxf(amu, fabsf(xsu[j*4+k]));
        }
    }
    #pragma unroll
    for (int o = 16; o > 0; o >>= 1) {
        amg = fmaxf(amg, __shfl_xor_sync(0xffffffffu, amg, o));
        amu = fmaxf(amu, __shfl_xor_sync(0xffffffffu, amu, o));
    }
    int w = threadIdx.x >> 5;
    if ((threadIdx.x & 31) == 0) { red_g[w] = amg; red_u[w] = amu; }
    __syncthreads();
    if (threadIdx.x == 0) {
        float mg = red_g[0], mu = red_u[0];
        #pragma unroll
        for (int i = 1; i < 8; i++) { mg = fmaxf(mg, red_g[i]); mu = fmaxf(mu, red_u[i]); }
        red_g[0] = mg; red_u[0] = mu;
    }
    __syncthreads();
    const float scg = fmaxf(__fmul_rn(red_g[0], rcp127()), 1e-8f);
    const float scu = fmaxf(__fmul_rn(red_u[0], rcp127()), 1e-8f);
    if (threadIdx.x == 0) { sg[row] = scg; su[row] = scu; }

    const float rscg = __fdiv_rn(1.0f, scg);
    const float rscu = __fdiv_rn(1.0f, scu);
    uint2* qg4 = (uint2*)(qg + (size_t)row * H_DIM);
    uint2* qu4 = (uint2*)(qu + (size_t)row * H_DIM);
    #pragma unroll
    for (int j = 0; j < 4; j++) {
        int idx = threadIdx.x + j * 256;
        float q0 = fminf(fmaxf(rintf(__fmul_rn(xsg[j*4+0], rscg)), -127.f), 127.f);
        float q1 = fminf(fmaxf(rintf(__fmul_rn(xsg[j*4+1], rscg)), -127.f), 127.f);
        float q2 = fminf(fmaxf(rintf(__fmul_rn(xsg[j*4+2], rscg)), -127.f), 127.f);
        float q3 = fminf(fmaxf(rintf(__fmul_rn(xsg[j*4+3], rscg)), -127.f), 127.f);
        qg4[idx] = pack4_bf16(q0, q1, q2, q3);
        q0 = fminf(fmaxf(rintf(__fmul_rn(xsu[j*4+0], rscu)), -127.f), 127.f);
        q1 = fminf(fmaxf(rintf(__fmul_rn(xsu[j*4+1], rscu)), -127.f), 127.f);
        q2 = fminf(fmaxf(rintf(__fmul_rn(xsu[j*4+2], rscu)), -127.f), 127.f);
        q3 = fminf(fmaxf(rintf(__fmul_rn(xsu[j*4+3], rscu)), -127.f), 127.f);
        qu4[idx] = pack4_bf16(q0, q1, q2, q3);
    }
}

// ============================================================================
// GEMM mainloop: CTA 128x128, warp 32x64 (8 warps 4Mx2N), K-chunk 64,
// 3-stage cp.async, ONE barrier/chunk, 2 CTAs/SM. cp.async issuance for the
// prefetch chunk is interleaved across the 4 k-steps (2 pairs per step).
// ============================================================================
#define KC 64
#define STAGE_BYTES 32768        // A 16KB + B 16KB
#define GEMM_SMEM_BYTES 98304    // 3 stages (x2 CTAs = 192KB <= 228KB)

__device__ __forceinline__ void gemm_body(
    char* sm,
    const __nv_bfloat16* __restrict__ A,
    const __nv_bfloat16* __restrict__ B,
    const float* __restrict__ aScale,
    const float* __restrict__ bScale,
    float* __restrict__ C,
    int N, int K, int m0, int n0)
{
    const uint32_t sbase = smem_to_u32(sm);
    const uint32_t SA = 0, SB = 16384;

    const int tid = threadIdx.x;
    const int wid = tid >> 5, lid = tid & 31;
    const int wm = (wid & 3) * 32;   // warp M offset
    const int wn = (wid >> 2) * 64;  // warp N offset

    const int nChunks = K / KC;

    // Issue the j-th pair (A+B, 16B each) of a chunk's loads into stage st.
    auto load_part = [&](int ch, int st, int j) {
        const int k0 = ch * KC;
        const uint32_t stoff = sbase + (uint32_t)st * STAGE_BYTES;
        int i = tid + j * 256;
        int r = i >> 3, c = i & 7;
        uint32_t sw = SMEM_SWIZZLE_128B(r * 128 + c * 16);
        CP_ASYNC_16(stoff + SA + sw, A + (size_t)(m0 + r) * K + k0 + c * 8);
        CP_ASYNC_16(stoff + SB + sw, B + (size_t)(n0 + r) * K + k0 + c * 8);
    };
    auto load_chunk = [&](int ch, int st) {
        #pragma unroll
        for (int j = 0; j < 4; j++) load_part(ch, st, j);
    };

    float acc[2][8][4];
    #pragma unroll
    for (int t = 0; t < 2; t++)
        #pragma unroll
        for (int n = 0; n < 8; n++)
            #pragma unroll
            for (int v = 0; v < 4; v++) acc[t][n][v] = 0.f;

    load_chunk(0, 0); CP_ASYNC_COMMIT();
    load_chunk(1, 1); CP_ASYNC_COMMIT();

    const int lrow = lid & 15;
    const int lhalf = (lid >> 4) * 16;

    int stage = 0;
    for (int ch = 0; ch < nChunks; ch++) {
        CP_ASYNC_WAIT_1();
        __syncthreads();   // single barrier per chunk; overwritten stage
                           // ((stage+2)%3) was consumed before this barrier.

        const uint32_t stoff = sbase + (uint32_t)stage * STAGE_BYTES;
        const bool prefetch = (ch + 2 < nChunks);
        int nst = stage + 2; if (nst >= 3) nst -= 3;

        #pragma unroll
        for (int s = 0; s < 4; s++) {
            const uint32_t kb = (uint32_t)(s * 32 + lhalf);
            uint32_t a[2][4];
            #pragma unroll
            for (int t = 0; t < 2; t++) {
                uint32_t off = SMEM_SWIZZLE_128B((uint32_t)(wm + t * 16 + lrow) * 128 + kb);
                ldsm_x4(a[t][0], a[t][1], a[t][2], a[t][3], stoff + SA + off);
            }
            uint32_t b[8][2];
            #pragma unroll
            for (int p = 0; p < 4; p++) {
                uint32_t off = SMEM_SWIZZLE_128B((uint32_t)(wn + p * 16 + lrow) * 128 + kb);
                uint32_t m0r, m1r, m2r, m3r;
                ldsm_x4(m0r, m1r, m2r, m3r, stoff + SB + off);
                b[2 * p][0] = m0r;     b[2 * p][1] = m2r;
                b[2 * p + 1][0] = m1r; b[2 * p + 1][1] = m3r;
            }
            // Interleave prefetch writes with this step's MMAs (smooths
            // crossbar write bursts against the LDSM read stream).
            if (prefetch) load_part(ch + 2, nst, s);
            #pragma unroll
            for (int t = 0; t < 2; t++)
                #pragma unroll
                for (int n = 0; n < 8; n++)
                    mma16816(acc[t][n], a[t], b[n][0], b[n][1]);
        }
        CP_ASYNC_COMMIT();
        stage = (stage + 1 == 3) ? 0 : stage + 1;
    }

    // Epilogue with fused scales: C = acc * aS[m] * bS[n] (left-assoc RN muls)
    #pragma unroll
    for (int t = 0; t < 2; t++) {
        const int r_lo = m0 + wm + t * 16 + (lid >> 2);
        const float s_lo = aScale[r_lo];
        const float s_hi = aScale[r_lo + 8];
        float* C_lo = C + (size_t)r_lo * N + n0 + wn;
        float* C_hi = C + (size_t)(r_lo + 8) * N + n0 + wn;
        #pragma unroll
        for (int n = 0; n < 8; n++) {
            const int colb = n * 8 + 2 * (lid & 3);
            const float b0 = bScale[n0 + wn + colb];
            const float b1 = bScale[n0 + wn + colb + 1];
            float2 vlo = make_float2(__fmul_rn(__fmul_rn(acc[t][n][0], s_lo), b0),
                                     __fmul_rn(__fmul_rn(acc[t][n][1], s_lo), b1));
            float2 vhi = make_float2(__fmul_rn(__fmul_rn(acc[t][n][2], s_hi), b0),
                                     __fmul_rn(__fmul_rn(acc[t][n][3], s_hi), b1));
            *(float2*)(C_lo + colb) = vlo;
            *(float2*)(C_hi + colb) = vhi;
        }
    }
}

// Single GEMM (down projection)
__global__ void __launch_bounds__(256, 2)
gemm_bf16_mma(const __nv_bfloat16* __restrict__ A,
              const __nv_bfloat16* __restrict__ B,
              const float* __restrict__ aScale,
              const float* __restrict__ bScale,
              float* __restrict__ C,
              int M, int N, int K)
{
    extern __shared__ __align__(1024) char sm[];
    gemm_body(sm, A, B, aScale, bScale, C, N, K,
              blockIdx.y * 128, blockIdx.x * 128);
}

// Dual GEMM: blockIdx.z selects {gate, up} problem set.
__global__ void __launch_bounds__(256, 2)
gemm_bf16_mma_dual(const __nv_bfloat16* __restrict__ A0,
                   const __nv_bfloat16* __restrict__ B0,
                   const float* __restrict__ aS0,
                   const float* __restrict__ bS0,
                   float* __restrict__ C0,
                   const __nv_bfloat16* __restrict__ A1,
                   const __nv_bfloat16* __restrict__ B1,
                   const float* __restrict__ aS1,
                   const float* __restrict__ bS1,
                   float* __restrict__ C1,
                   int M, int N, int K)
{
    extern __shared__ __align__(1024) char sm[];
    const bool z = (blockIdx.z != 0);
    gemm_body(sm,
              z ? A1 : A0, z ? B1 : B0,
              z ? aS1 : aS0, z ? bS1 : bS0,
              z ? C1 : C0,
              N, K, blockIdx.y * 128, blockIdx.x * 128);
}

// ============================================================================
// Kernel 3: SwiGLU (XLA silu) + clip + bf16 + requant -> bf16 ints (one pass)
// ============================================================================
__global__ void __launch_bounds__(256) swiglu_quant_kernel(
    const float* __restrict__ gate,
    const float* __restrict__ up,
    const float* __restrict__ invi,
    __nv_bfloat16* __restrict__ qi,
    float* __restrict__ si)
{
    __shared__ float red[8];

    const int row = blockIdx.x;
    const float4* gr = (const float4*)(gate + (size_t)row * I_DIM);
    const float4* ur = (const float4*)(up + (size_t)row * I_DIM);
    const float4* iv4 = (const float4*)invi;

    float prod[8];
    float am = 0.f;
    #pragma unroll
    for (int j = 0; j < 2; j++) {
        int idx = threadIdx.x + j * 256;
        float4 g = gr[idx];
        float4 u = ur[idx];
        float4 iv = iv4[idx];
        float v0 = fminf(fmaxf(__fmul_rn(xla_silu(g.x), u.x), -10.f), 10.f);
        float v1 = fminf(fmaxf(__fmul_rn(xla_silu(g.y), u.y), -10.f), 10.f);
        float v2 = fminf(fmaxf(__fmul_rn(xla_silu(g.z), u.z), -10.f), 10.f);
        float v3 = fminf(fmaxf(__fmul_rn(xla_silu(g.w), u.w), -10.f), 10.f);
        float f0 = __bfloat162float(__float2bfloat16(v0));
        float f1 = __bfloat162float(__float2bfloat16(v1));
        float f2 = __bfloat162float(__float2bfloat16(v2));
        float f3 = __bfloat162float(__float2bfloat16(v3));
        prod[j*4+0] = __fmul_rn(f0, iv.x);
        prod[j*4+1] = __fmul_rn(f1, iv.y);
        prod[j*4+2] = __fmul_rn(f2, iv.z);
        prod[j*4+3] = __fmul_rn(f3, iv.w);
        #pragma unroll
        for (int k = 0; k < 4; k++) am = fmaxf(am, fabsf(prod[j*4+k]));
    }
    #pragma unroll
    for (int o = 16; o > 0; o >>= 1)
        am = fmaxf(am, __shfl_xor_sync(0xffffffffu, am, o));
    int w = threadIdx.x >> 5;
    if ((threadIdx.x & 31) == 0) red[w] = am;
    __syncthreads();
    if (threadIdx.x == 0) {
        float m = red[0];
        #pragma unroll
        for (int i = 1; i < 8; i++) m = fmaxf(m, red[i]);
        red[0] = m;
    }
    __syncthreads();
    const float sc = fmaxf(__fmul_rn(red[0], rcp127()), 1e-8f);
    if (threadIdx.x == 0) si[row] = sc;
    const float rsc = __fdiv_rn(1.0f, sc);
    uint2* qi4 = (uint2*)(qi + (size_t)row * I_DIM);
    #pragma unroll
    for (int j = 0; j < 2; j++) {
        int idx = threadIdx.x + j * 256;
        float q0 = fminf(fmaxf(rintf(__fmul_rn(prod[j*4+0], rsc)), -127.f), 127.f);
        float q1 = fminf(fmaxf(rintf(__fmul_rn(prod[j*4+1], rsc)), -127.f), 127.f);
        float q2 = fminf(fmaxf(rintf(__fmul_rn(prod[j*4+2], rsc)), -127.f), 127.f);
        float q3 = fminf(fmaxf(rintf(__fmul_rn(prod[j*4+3], rsc)), -127.f), 127.f);
        qi4[idx] = pack4_bf16(q0, q1, q2, q3);
    }
}

// ============================================================================
// Launch (capture-fork: cvt on side stream concurrent with quant_x)
// ============================================================================
extern "C" void kernel_launch(void* const* d_in, const int* in_sizes, int n_in,
                              void* d_out, int out_size)
{
    const float* x       = (const float*)d_in[0];
    const float* w_gate  = (const float*)d_in[1];
    const float* s_wgate = (const float*)d_in[2];
    const float* w_up    = (const float*)d_in[3];
    const float* s_wup   = (const float*)d_in[4];
    const float* w_down  = (const float*)d_in[5];
    const float* s_wdown = (const float*)d_in[6];
    const float* inv_g   = (const float*)d_in[7];
    const float* inv_u   = (const float*)d_in[8];
    const float* inv_i   = (const float*)d_in[9];
    float* out = (float*)d_out;

    void *p_qg, *p_qu, *p_wg, *p_wu, *p_wd, *p_gate, *p_up, *p_qi, *p_sg, *p_su, *p_si;
    cudaGetSymbolAddress(&p_qg, g_qg);
    cudaGetSymbolAddress(&p_qu, g_qu);
    cudaGetSymbolAddress(&p_wg, g_wg);
    cudaGetSymbolAddress(&p_wu, g_wu);
    cudaGetSymbolAddress(&p_wd, g_wd);
    cudaGetSymbolAddress(&p_gate, g_gate);
    cudaGetSymbolAddress(&p_up, g_up);
    cudaGetSymbolAddress(&p_qi, g_qi);
    cudaGetSymbolAddress(&p_sg, g_sg);
    cudaGetSymbolAddress(&p_su, g_su);
    cudaGetSymbolAddress(&p_si, g_si);

    cudaFuncSetAttribute(gemm_bf16_mma,
                         cudaFuncAttributeMaxDynamicSharedMemorySize,
                         GEMM_SMEM_BYTES);
    cudaFuncSetAttribute(gemm_bf16_mma_dual,
                         cudaFuncAttributeMaxDynamicSharedMemorySize,
                         GEMM_SMEM_BYTES);

    // One-time side stream + events (host-side objects only; no device memory)
    static cudaStream_t s2 = nullptr;
    static cudaEvent_t evFork = nullptr, evJoin = nullptr;
    if (!s2) {
        cudaStreamCreateWithFlags(&s2, cudaStreamNonBlocking);
        cudaEventCreateWithFlags(&evFork, cudaEventDisableTiming);
        cudaEventCreateWithFlags(&evJoin, cudaEventDisableTiming);
    }

    // Fork: cvt (weights) runs on s2 concurrently with quant_x (x) on main.
    cudaEventRecord(evFork, 0);
    cudaStreamWaitEvent(s2, evFork, 0);
    cvt_weights_kernel<<<1024, 256, 0, s2>>>(
        (const float4*)w_gate, (const float4*)w_up, (const float4*)w_down,
        (uint2*)p_wg, (uint2*)p_wu, (uint2*)p_wd);
    cudaEventRecord(evJoin, s2);

    quant_x_kernel<<<T_TOK, 256>>>(x, inv_g, inv_u,
                                   (__nv_bfloat16*)p_qg, (__nv_bfloat16*)p_qu,
                                   (float*)p_sg, (float*)p_su);

    // Join: GEMMs need both quant_x (main) and cvt (s2) results.
    cudaStreamWaitEvent(0, evJoin, 0);

    // gate & up GEMMs merged into ONE launch (z selects problem)
    dim3 grid1(I_DIM / 128, T_TOK / 128, 2);
    gemm_bf16_mma_dual<<<grid1, 256, GEMM_SMEM_BYTES>>>(
        (const __nv_bfloat16*)p_qg, (const __nv_bfloat16*)p_wg,
        (const float*)p_sg, s_wgate, (float*)p_gate,
        (const __nv_bfloat16*)p_qu, (const __nv_bfloat16*)p_wu,
        (const float*)p_su, s_wup, (float*)p_up,
        T_TOK, I_DIM, H_DIM);

    // swiglu + clip + requant
    swiglu_quant_kernel<<<T_TOK, 256>>>((const float*)p_gate, (const float*)p_up,
                                        inv_i, (__nv_bfloat16*)p_qi, (float*)p_si);

    // down GEMM straight into d_out: [T,H] = [T,I] @ [H,I]^T
    dim3 grid3(H_DIM / 128, T_TOK / 128);
    gemm_bf16_mma<<<grid3, 256, GEMM_SMEM_BYTES>>>(
        (const __nv_bfloat16*)p_qi, (const __nv_bfloat16*)p_wd,
        (const float*)p_si, s_wdown, out, T_TOK, H_DIM, I_DIM);
}

// round 17
// speedup vs baseline: 1.1102x; 1.1102x over previous
#include <cuda_runtime.h>
#include <cuda_bf16.h>
#include <cstdint>
#include <math.h>

// ============================================================================
// Problem dims (fixed by the dataset): x [2,4096,4096] -> T=8192 tokens
// ============================================================================
#define T_TOK 8192
#define H_DIM 4096
#define I_DIM 2048

// Harness ptxas targets plain sm_103 (no 'a'): baseline-ISA tensor path.
// R17 = R15 (best; R16's mainloop scheduling tweaks regressed and are fully
// reverted) + split weight-convert: gate/up weights convert on s2 before
// GEMM1 (now shorter than quant_x -> full overlap); w_down converts on s2
// DURING GEMM1 and joins before GEMM3 (13us of DRAM moved off critical path).
//
// Numerics model (XLA CPU fast-math = arcp+contract), validated in R6:
//  - scale = amax * RN(1/127), fmax 1e-8
//  - q = xs * (1.0/scale)_exact_div, rintf (round-half-even)
//  - silu: logistic = 0.5 + 0.5*tanh(0.5x), EmitFastTanh poly, FMA-contracted

static __device__ __forceinline__ float rcp127() { return 1.0f / 127.0f; }

__device__ __forceinline__ float xla_fast_tanh(float x) {
    const float kMax = 7.90531110763549805f;
    float cl = fminf(fmaxf(x, -kMax), kMax);
    float x2 = __fmul_rn(cl, cl);
    float p = -2.76076847742355e-16f;
    p = __fmaf_rn(x2, p, 2.00018790482477e-13f);
    p = __fmaf_rn(x2, p, -8.60467152213735e-11f);
    p = __fmaf_rn(x2, p, 5.12229709037114e-08f);
    p = __fmaf_rn(x2, p, 1.48572235717979e-05f);
    p = __fmaf_rn(x2, p, 6.37261928875436e-04f);
    p = __fmaf_rn(x2, p, 4.89352455891786e-03f);
    p = __fmul_rn(cl, p);
    float q = 1.19825839466702e-06f;
    q = __fmaf_rn(x2, q, 1.18534705686654e-04f);
    q = __fmaf_rn(x2, q, 2.26843463243900e-03f);
    q = __fmaf_rn(x2, q, 4.89352518554385e-03f);
    return (fabsf(x) < 0.0004f) ? x : __fdiv_rn(p, q);
}

__device__ __forceinline__ float xla_silu(float x) {
    float t = xla_fast_tanh(__fmul_rn(0.5f, x));
    float sig = __fmaf_rn(0.5f, t, 0.5f);
    return __fmul_rn(x, sig);
}

// ============================================================================
// PTX helpers
// ============================================================================
__device__ __forceinline__ uint32_t smem_to_u32(const void* smem_ptr) {
    uint32_t addr;
    asm("{ .reg .u64 tmp; cvta.to.shared.u64 tmp, %1; cvt.u32.u64 %0, tmp; }"
        : "=r"(addr) : "l"(smem_ptr));
    return addr;
}

#define SMEM_SWIZZLE_128B(byte_offset) \
    ((uint32_t)(byte_offset) ^ ((((uint32_t)(byte_offset)) >> 3) & 0x70u))

#define CP_ASYNC_16(smem_u32, gptr) \
    asm volatile("cp.async.cg.shared.global [%0], [%1], 16;" \
        :: "r"(smem_u32), "l"(gptr) : "memory")

#define CP_ASYNC_COMMIT() asm volatile("cp.async.commit_group;" ::: "memory")
#define CP_ASYNC_WAIT_1() asm volatile("cp.async.wait_group 1;" ::: "memory")

__device__ __forceinline__ void ldsm_x4(uint32_t& r0, uint32_t& r1,
                                        uint32_t& r2, uint32_t& r3,
                                        uint32_t smem_addr) {
    asm volatile(
        "ldmatrix.sync.aligned.m8n8.x4.shared.b16 {%0,%1,%2,%3}, [%4];"
        : "=r"(r0), "=r"(r1), "=r"(r2), "=r"(r3)
        : "r"(smem_addr));
}

__device__ __forceinline__ void mma16816(float* c, const uint32_t* a,
                                         uint32_t b0, uint32_t b1) {
    asm volatile(
        "mma.sync.aligned.m16n8k16.row.col.f32.bf16.bf16.f32 "
        "{%0,%1,%2,%3}, {%4,%5,%6,%7}, {%8,%9}, {%0,%1,%2,%3};"
        : "+f"(c[0]), "+f"(c[1]), "+f"(c[2]), "+f"(c[3])
        : "r"(a[0]), "r"(a[1]), "r"(a[2]), "r"(a[3]), "r"(b0), "r"(b1));
}

// ============================================================================
// Device scratch (static globals: allocation-guard-safe)
// ============================================================================
__device__ __nv_bfloat16 g_qg[(size_t)T_TOK * H_DIM];
__device__ __nv_bfloat16 g_qu[(size_t)T_TOK * H_DIM];
__device__ __nv_bfloat16 g_wg[(size_t)I_DIM * H_DIM];
__device__ __nv_bfloat16 g_wu[(size_t)I_DIM * H_DIM];
__device__ __nv_bfloat16 g_wd[(size_t)H_DIM * I_DIM];
__device__ float g_gate[(size_t)T_TOK * I_DIM];
__device__ float g_up[(size_t)T_TOK * I_DIM];
__device__ __nv_bfloat16 g_qi[(size_t)T_TOK * I_DIM];
__device__ float g_sg[T_TOK];
__device__ float g_su[T_TOK];
__device__ float g_si[T_TOK];

// Pack 4 floats -> 4 bf16 in a uint2
__device__ __forceinline__ uint2 pack4_bf16(float a, float b, float c, float d) {
    __nv_bfloat162 lo = __floats2bfloat162_rn(a, b);
    __nv_bfloat162 hi = __floats2bfloat162_rn(c, d);
    uint2 r;
    r.x = *(uint32_t*)&lo;
    r.y = *(uint32_t*)&hi;
    return r;
}

// ============================================================================
// Kernel 0a: f32 -> bf16 convert for gate+up weights (needed before GEMM1)
// ============================================================================
#define W_N4 (I_DIM * H_DIM / 4)
__global__ void cvt_weights_gu_kernel(const float4* __restrict__ in0,
                                      const float4* __restrict__ in1,
                                      uint2* __restrict__ out0,
                                      uint2* __restrict__ out1)
{
    int i = blockIdx.x * blockDim.x + threadIdx.x;
    int stride = gridDim.x * blockDim.x;
    for (; i < 2 * W_N4; i += stride) {
        const float4* in; uint2* out; int j;
        if (i < W_N4) { in = in0; out = out0; j = i; }
        else          { in = in1; out = out1; j = i - W_N4; }
        float4 v = in[j];
        out[j] = pack4_bf16(v.x, v.y, v.z, v.w);
    }
}

// Kernel 0b: f32 -> bf16 convert for w_down (needed only before GEMM3;
// runs on s2 overlapping GEMM1)
__global__ void cvt_weights_d_kernel(const float4* __restrict__ in,
                                     uint2* __restrict__ out)
{
    int i = blockIdx.x * blockDim.x + threadIdx.x;
    int stride = gridDim.x * blockDim.x;
    for (; i < W_N4; i += stride) {
        float4 v = in[i];
        out[i] = pack4_bf16(v.x, v.y, v.z, v.w);
    }
}

// ============================================================================
// Kernel 1: per-token dual dynamic quant of x -> bf16 ints (one pass)
// ============================================================================
__global__ void __launch_bounds__(256) quant_x_kernel(
    const float* __restrict__ x,
    const float* __restrict__ invg,
    const float* __restrict__ invu,
    __nv_bfloat16* __restrict__ qg,
    __nv_bfloat16* __restrict__ qu,
    float* __restrict__ sg,
    float* __restrict__ su)
{
    __shared__ float red_g[8];
    __shared__ float red_u[8];

    const int row = blockIdx.x;
    const float4* xr = (const float4*)(x + (size_t)row * H_DIM);
    const float4* g4 = (const float4*)invg;
    const float4* u4 = (const float4*)invu;

    float xsg[16], xsu[16];
    float amg = 0.f, amu = 0.f;
    #pragma unroll
    for (int j = 0; j < 4; j++) {
        int idx = threadIdx.x + j * 256;
        float4 v = xr[idx];
        float4 gi = g4[idx];
        float4 ui = u4[idx];
        float f0 = __bfloat162float(__float2bfloat16(v.x));
        float f1 = __bfloat162float(__float2bfloat16(v.y));
        float f2 = __bfloat162float(__float2bfloat16(v.z));
        float f3 = __bfloat162float(__float2bfloat16(v.w));
        xsg[j*4+0] = __fmul_rn(f0, gi.x); xsg[j*4+1] = __fmul_rn(f1, gi.y);
        xsg[j*4+2] = __fmul_rn(f2, gi.z); xsg[j*4+3] = __fmul_rn(f3, gi.w);
        xsu[j*4+0] = __fmul_rn(f0, ui.x); xsu[j*4+1] = __fmul_rn(f1, ui.y);
        xsu[j*4+2] = __fmul_rn(f2, ui.z); xsu[j*4+3] = __fmul_rn(f3, ui.w);
        #pragma unroll
        for (int k = 0; k < 4; k++) {
            amg = fmaxf(amg, fabsf(xsg[j*4+k]));
            amu = fmaxf(amu, fabsf(xsu[j*4+k]));
        }
    }
    #pragma unroll
    for (int o = 16; o > 0; o >>= 1) {
        amg = fmaxf(amg, __shfl_xor_sync(0xffffffffu, amg, o));
        amu = fmaxf(amu, __shfl_xor_sync(0xffffffffu, amu, o));
    }
    int w = threadIdx.x >> 5;
    if ((threadIdx.x & 31) == 0) { red_g[w] = amg; red_u[w] = amu; }
    __syncthreads();
    if (threadIdx.x == 0) {
        float mg = red_g[0], mu = red_u[0];
        #pragma unroll
        for (int i = 1; i < 8; i++) { mg = fmaxf(mg, red_g[i]); mu = fmaxf(mu, red_u[i]); }
        red_g[0] = mg; red_u[0] = mu;
    }
    __syncthreads();
    const float scg = fmaxf(__fmul_rn(red_g[0], rcp127()), 1e-8f);
    const float scu = fmaxf(__fmul_rn(red_u[0], rcp127()), 1e-8f);
    if (threadIdx.x == 0) { sg[row] = scg; su[row] = scu; }

    const float rscg = __fdiv_rn(1.0f, scg);
    const float rscu = __fdiv_rn(1.0f, scu);
    uint2* qg4 = (uint2*)(qg + (size_t)row * H_DIM);
    uint2* qu4 = (uint2*)(qu + (size_t)row * H_DIM);
    #pragma unroll
    for (int j = 0; j < 4; j++) {
        int idx = threadIdx.x + j * 256;
        float q0 = fminf(fmaxf(rintf(__fmul_rn(xsg[j*4+0], rscg)), -127.f), 127.f);
        float q1 = fminf(fmaxf(rintf(__fmul_rn(xsg[j*4+1], rscg)), -127.f), 127.f);
        float q2 = fminf(fmaxf(rintf(__fmul_rn(xsg[j*4+2], rscg)), -127.f), 127.f);
        float q3 = fminf(fmaxf(rintf(__fmul_rn(xsg[j*4+3], rscg)), -127.f), 127.f);
        qg4[idx] = pack4_bf16(q0, q1, q2, q3);
        q0 = fminf(fmaxf(rintf(__fmul_rn(xsu[j*4+0], rscu)), -127.f), 127.f);
        q1 = fminf(fmaxf(rintf(__fmul_rn(xsu[j*4+1], rscu)), -127.f), 127.f);
        q2 = fminf(fmaxf(rintf(__fmul_rn(xsu[j*4+2], rscu)), -127.f), 127.f);
        q3 = fminf(fmaxf(rintf(__fmul_rn(xsu[j*4+3], rscu)), -127.f), 127.f);
        qu4[idx] = pack4_bf16(q0, q1, q2, q3);
    }
}

// ============================================================================
// GEMM mainloop (R15-converged, DO NOT MODIFY): CTA 128x128, warp 32x64
// (8 warps 4Mx2N), K-chunk 64, 3-stage cp.async, ONE barrier/chunk, 2 CTAs/SM.
// ============================================================================
#define KC 64
#define STAGE_BYTES 32768        // A 16KB + B 16KB
#define GEMM_SMEM_BYTES 98304    // 3 stages (x2 CTAs = 192KB <= 228KB)

__device__ __forceinline__ void gemm_body(
    char* sm,
    const __nv_bfloat16* __restrict__ A,
    const __nv_bfloat16* __restrict__ B,
    const float* __restrict__ aScale,
    const float* __restrict__ bScale,
    float* __restrict__ C,
    int N, int K, int m0, int n0)
{
    const uint32_t sbase = smem_to_u32(sm);
    const uint32_t SA = 0, SB = 16384;

    const int tid = threadIdx.x;
    const int wid = tid >> 5, lid = tid & 31;
    const int wm = (wid & 3) * 32;   // warp M offset
    const int wn = (wid >> 2) * 64;  // warp N offset

    const int nChunks = K / KC;

    auto load_chunk = [&](int ch, int st) {
        const int k0 = ch * KC;
        const uint32_t stoff = sbase + (uint32_t)st * STAGE_BYTES;
        #pragma unroll
        for (int j = 0; j < 4; j++) {
            int i = tid + j * 256;
            int r = i >> 3, c = i & 7;
            uint32_t sw = SMEM_SWIZZLE_128B(r * 128 + c * 16);
            CP_ASYNC_16(stoff + SA + sw, A + (size_t)(m0 + r) * K + k0 + c * 8);
            CP_ASYNC_16(stoff + SB + sw, B + (size_t)(n0 + r) * K + k0 + c * 8);
        }
    };

    float acc[2][8][4];
    #pragma unroll
    for (int t = 0; t < 2; t++)
        #pragma unroll
        for (int n = 0; n < 8; n++)
            #pragma unroll
            for (int v = 0; v < 4; v++) acc[t][n][v] = 0.f;

    load_chunk(0, 0); CP_ASYNC_COMMIT();
    load_chunk(1, 1); CP_ASYNC_COMMIT();

    const int lrow = lid & 15;
    const int lhalf = (lid >> 4) * 16;

    int stage = 0;
    for (int ch = 0; ch < nChunks; ch++) {
        CP_ASYNC_WAIT_1();
        __syncthreads();   // single barrier per chunk; overwritten stage
                           // ((stage+2)%3) was consumed before this barrier.

        const uint32_t stoff = sbase + (uint32_t)stage * STAGE_BYTES;
        #pragma unroll
        for (int s = 0; s < 4; s++) {
            const uint32_t kb = (uint32_t)(s * 32 + lhalf);
            uint32_t a[2][4];
            #pragma unroll
            for (int t = 0; t < 2; t++) {
                uint32_t off = SMEM_SWIZZLE_128B((uint32_t)(wm + t * 16 + lrow) * 128 + kb);
                ldsm_x4(a[t][0], a[t][1], a[t][2], a[t][3], stoff + SA + off);
            }
            uint32_t b[8][2];
            #pragma unroll
            for (int p = 0; p < 4; p++) {
                uint32_t off = SMEM_SWIZZLE_128B((uint32_t)(wn + p * 16 + lrow) * 128 + kb);
                uint32_t m0r, m1r, m2r, m3r;
                ldsm_x4(m0r, m1r, m2r, m3r, stoff + SB + off);
                b[2 * p][0] = m0r;     b[2 * p][1] = m2r;
                b[2 * p + 1][0] = m1r; b[2 * p + 1][1] = m3r;
            }
            #pragma unroll
            for (int t = 0; t < 2; t++)
                #pragma unroll
                for (int n = 0; n < 8; n++)
                    mma16816(acc[t][n], a[t], b[n][0], b[n][1]);
        }

        if (ch + 2 < nChunks) {
            int nst = stage + 2; if (nst >= 3) nst -= 3;
            load_chunk(ch + 2, nst);
        }
        CP_ASYNC_COMMIT();
        stage = (stage + 1 == 3) ? 0 : stage + 1;
    }

    // Epilogue with fused scales: C = acc * aS[m] * bS[n] (left-assoc RN muls)
    #pragma unroll
    for (int t = 0; t < 2; t++) {
        const int r_lo = m0 + wm + t * 16 + (lid >> 2);
        const float s_lo = aScale[r_lo];
        const float s_hi = aScale[r_lo + 8];
        float* C_lo = C + (size_t)r_lo * N + n0 + wn;
        float* C_hi = C + (size_t)(r_lo + 8) * N + n0 + wn;
        #pragma unroll
        for (int n = 0; n < 8; n++) {
            const int colb = n * 8 + 2 * (lid & 3);
            const float b0 = bScale[n0 + wn + colb];
            const float b1 = bScale[n0 + wn + colb + 1];
            float2 vlo = make_float2(__fmul_rn(__fmul_rn(acc[t][n][0], s_lo), b0),
                                     __fmul_rn(__fmul_rn(acc[t][n][1], s_lo), b1));
            float2 vhi = make_float2(__fmul_rn(__fmul_rn(acc[t][n][2], s_hi), b0),
                                     __fmul_rn(__fmul_rn(acc[t][n][3], s_hi), b1));
            *(float2*)(C_lo + colb) = vlo;
            *(float2*)(C_hi + colb) = vhi;
        }
    }
}

// Single GEMM (down projection)
__global__ void __launch_bounds__(256, 2)
gemm_bf16_mma(const __nv_bfloat16* __restrict__ A,
              const __nv_bfloat16* __restrict__ B,
              const float* __restrict__ aScale,
              const float* __restrict__ bScale,
              float* __restrict__ C,
              int M, int N, int K)
{
    extern __shared__ __align__(1024) char sm[];
    gemm_body(sm, A, B, aScale, bScale, C, N, K,
              blockIdx.y * 128, blockIdx.x * 128);
}

// Dual GEMM: blockIdx.z selects {gate, up} problem set.
__global__ void __launch_bounds__(256, 2)
gemm_bf16_mma_dual(const __nv_bfloat16* __restrict__ A0,
                   const __nv_bfloat16* __restrict__ B0,
                   const float* __restrict__ aS0,
                   const float* __restrict__ bS0,
                   float* __restrict__ C0,
                   const __nv_bfloat16* __restrict__ A1,
                   const __nv_bfloat16* __restrict__ B1,
                   const float* __restrict__ aS1,
                   const float* __restrict__ bS1,
                   float* __restrict__ C1,
                   int M, int N, int K)
{
    extern __shared__ __align__(1024) char sm[];
    const bool z = (blockIdx.z != 0);
    gemm_body(sm,
              z ? A1 : A0, z ? B1 : B0,
              z ? aS1 : aS0, z ? bS1 : bS0,
              z ? C1 : C0,
              N, K, blockIdx.y * 128, blockIdx.x * 128);
}

// ============================================================================
// Kernel 3: SwiGLU (XLA silu) + clip + bf16 + requant -> bf16 ints (one pass)
// ============================================================================
__global__ void __launch_bounds__(256) swiglu_quant_kernel(
    const float* __restrict__ gate,
    const float* __restrict__ up,
    const float* __restrict__ invi,
    __nv_bfloat16* __restrict__ qi,
    float* __restrict__ si)
{
    __shared__ float red[8];

    const int row = blockIdx.x;
    const float4* gr = (const float4*)(gate + (size_t)row * I_DIM);
    const float4* ur = (const float4*)(up + (size_t)row * I_DIM);
    const float4* iv4 = (const float4*)invi;

    float prod[8];
    float am = 0.f;
    #pragma unroll
    for (int j = 0; j < 2; j++) {
        int idx = threadIdx.x + j * 256;
        float4 g = gr[idx];
        float4 u = ur[idx];
        float4 iv = iv4[idx];
        float v0 = fminf(fmaxf(__fmul_rn(xla_silu(g.x), u.x), -10.f), 10.f);
        float v1 = fminf(fmaxf(__fmul_rn(xla_silu(g.y), u.y), -10.f), 10.f);
        float v2 = fminf(fmaxf(__fmul_rn(xla_silu(g.z), u.z), -10.f), 10.f);
        float v3 = fminf(fmaxf(__fmul_rn(xla_silu(g.w), u.w), -10.f), 10.f);
        float f0 = __bfloat162float(__float2bfloat16(v0));
        float f1 = __bfloat162float(__float2bfloat16(v1));
        float f2 = __bfloat162float(__float2bfloat16(v2));
        float f3 = __bfloat162float(__float2bfloat16(v3));
        prod[j*4+0] = __fmul_rn(f0, iv.x);
        prod[j*4+1] = __fmul_rn(f1, iv.y);
        prod[j*4+2] = __fmul_rn(f2, iv.z);
        prod[j*4+3] = __fmul_rn(f3, iv.w);
        #pragma unroll
        for (int k = 0; k < 4; k++) am = fmaxf(am, fabsf(prod[j*4+k]));
    }
    #pragma unroll
    for (int o = 16; o > 0; o >>= 1)
        am = fmaxf(am, __shfl_xor_sync(0xffffffffu, am, o));
    int w = threadIdx.x >> 5;
    if ((threadIdx.x & 31) == 0) red[w] = am;
    __syncthreads();
    if (threadIdx.x == 0) {
        float m = red[0];
        #pragma unroll
        for (int i = 1; i < 8; i++) m = fmaxf(m, red[i]);
        red[0] = m;
    }
    __syncthreads();
    const float sc = fmaxf(__fmul_rn(red[0], rcp127()), 1e-8f);
    if (threadIdx.x == 0) si[row] = sc;
    const float rsc = __fdiv_rn(1.0f, sc);
    uint2* qi4 = (uint2*)(qi + (size_t)row * I_DIM);
    #pragma unroll
    for (int j = 0; j < 2; j++) {
        int idx = threadIdx.x + j * 256;
        float q0 = fminf(fmaxf(rintf(__fmul_rn(prod[j*4+0], rsc)), -127.f), 127.f);
        float q1 = fminf(fmaxf(rintf(__fmul_rn(prod[j*4+1], rsc)), -127.f), 127.f);
        float q2 = fminf(fmaxf(rintf(__fmul_rn(prod[j*4+2], rsc)), -127.f), 127.f);
        float q3 = fminf(fmaxf(rintf(__fmul_rn(prod[j*4+3], rsc)), -127.f), 127.f);
        qi4[idx] = pack4_bf16(q0, q1, q2, q3);
    }
}

// ============================================================================
// Launch (capture-fork: cvt_gu || quant_x; cvt_d overlaps GEMM1)
// ============================================================================
extern "C" void kernel_launch(void* const* d_in, const int* in_sizes, int n_in,
                              void* d_out, int out_size)
{
    const float* x       = (const float*)d_in[0];
    const float* w_gate  = (const float*)d_in[1];
    const float* s_wgate = (const float*)d_in[2];
    const float* w_up    = (const float*)d_in[3];
    const float* s_wup   = (const float*)d_in[4];
    const float* w_down  = (const float*)d_in[5];
    const float* s_wdown = (const float*)d_in[6];
    const float* inv_g   = (const float*)d_in[7];
    const float* inv_u   = (const float*)d_in[8];
    const float* inv_i   = (const float*)d_in[9];
    float* out = (float*)d_out;

    void *p_qg, *p_qu, *p_wg, *p_wu, *p_wd, *p_gate, *p_up, *p_qi, *p_sg, *p_su, *p_si;
    cudaGetSymbolAddress(&p_qg, g_qg);
    cudaGetSymbolAddress(&p_qu, g_qu);
    cudaGetSymbolAddress(&p_wg, g_wg);
    cudaGetSymbolAddress(&p_wu, g_wu);
    cudaGetSymbolAddress(&p_wd, g_wd);
    cudaGetSymbolAddress(&p_gate, g_gate);
    cudaGetSymbolAddress(&p_up, g_up);
    cudaGetSymbolAddress(&p_qi, g_qi);
    cudaGetSymbolAddress(&p_sg, g_sg);
    cudaGetSymbolAddress(&p_su, g_su);
    cudaGetSymbolAddress(&p_si, g_si);

    cudaFuncSetAttribute(gemm_bf16_mma,
                         cudaFuncAttributeMaxDynamicSharedMemorySize,
                         GEMM_SMEM_BYTES);
    cudaFuncSetAttribute(gemm_bf16_mma_dual,
                         cudaFuncAttributeMaxDynamicSharedMemorySize,
                         GEMM_SMEM_BYTES);

    // One-time side stream + events (host-side objects only; no device memory)
    static cudaStream_t s2 = nullptr;
    static cudaEvent_t evFork = nullptr, evJoinGU = nullptr, evJoinD = nullptr;
    if (!s2) {
        cudaStreamCreateWithFlags(&s2, cudaStreamNonBlocking);
        cudaEventCreateWithFlags(&evFork, cudaEventDisableTiming);
        cudaEventCreateWithFlags(&evJoinGU, cudaEventDisableTiming);
        cudaEventCreateWithFlags(&evJoinD, cudaEventDisableTiming);
    }

    // Fork: cvt gate/up weights (~27us) on s2 concurrent with quant_x (41us).
    cudaEventRecord(evFork, 0);
    cudaStreamWaitEvent(s2, evFork, 0);
    cvt_weights_gu_kernel<<<1024, 256, 0, s2>>>(
        (const float4*)w_gate, (const float4*)w_up,
        (uint2*)p_wg, (uint2*)p_wu);
    cudaEventRecord(evJoinGU, s2);
    // cvt w_down on s2: overlaps GEMM1 (only needed before GEMM3).
    cvt_weights_d_kernel<<<512, 256, 0, s2>>>(
        (const float4*)w_down, (uint2*)p_wd);
    cudaEventRecord(evJoinD, s2);

    quant_x_kernel<<<T_TOK, 256>>>(x, inv_g, inv_u,
                                   (__nv_bfloat16*)p_qg, (__nv_bfloat16*)p_qu,
                                   (float*)p_sg, (float*)p_su);

    // Join for GEMM1: needs quant_x (main) + gate/up weights (s2).
    cudaStreamWaitEvent(0, evJoinGU, 0);

    // gate & up GEMMs merged into ONE launch (z selects problem)
    dim3 grid1(I_DIM / 128, T_TOK / 128, 2);
    gemm_bf16_mma_dual<<<grid1, 256, GEMM_SMEM_BYTES>>>(
        (const __nv_bfloat16*)p_qg, (const __nv_bfloat16*)p_wg,
        (const float*)p_sg, s_wgate, (float*)p_gate,
        (const __nv_bfloat16*)p_qu, (const __nv_bfloat16*)p_wu,
        (const float*)p_su, s_wup, (float*)p_up,
        T_TOK, I_DIM, H_DIM);

    // swiglu + clip + requant
    swiglu_quant_kernel<<<T_TOK, 256>>>((const float*)p_gate, (const float*)p_up,
                                        inv_i, (__nv_bfloat16*)p_qi, (float*)p_si);

    // Join for GEMM3: w_down conversion (finished long ago, zero-cost wait).
    cudaStreamWaitEvent(0, evJoinD, 0);

    // down GEMM straight into d_out: [T,H] = [T,I] @ [H,I]^T
    dim3 grid3(H_DIM / 128, T_TOK / 128);
    gemm_bf16_mma<<<grid3, 256, GEMM_SMEM_BYTES>>>(
        (const __nv_bfloat16*)p_qi, (const __nv_bfloat16*)p_wd,
        (const float*)p_si, s_wdown, out, T_TOK, H_DIM, I_DIM);
}